// round 4
// baseline (speedup 1.0000x reference)
#include <cuda_runtime.h>
#include <cuda_bf16.h>

#define BN_ 640
#define TSTEPS 127
#define AA_ 6

typedef unsigned long long u64;

// scratch (device global: no allocations allowed)
__device__ float g_state_emb[BN_ * 64];

__device__ __forceinline__ float fsigm(float x) {
    return 1.f / (1.f + expf(-x));
}
__device__ __forceinline__ void fma2(u64& d, u64 a, u64 b) {
    asm("fma.rn.f32x2 %0, %1, %2, %0;" : "+l"(d) : "l"(a), "l"(b));
}
__device__ __forceinline__ float hsum2(u64 v) {
    unsigned lo, hi;
    asm("mov.b64 {%0,%1}, %2;" : "=r"(lo), "=r"(hi) : "l"(v));
    return __uint_as_float(lo) + __uint_as_float(hi);
}

// ---------------------------------------------------------------------------
// Encoder v2: 160 blocks x 256 threads, 4 rows/block. Conv weights staged in
// smem; conv as sliding-window row tasks; fc warp-cooperative + coalesced.
// ---------------------------------------------------------------------------
__global__ void __launch_bounds__(256) encoder_kernel(
    const float* __restrict__ s_h, const int* __restrict__ a_h,
    const float* __restrict__ w1, const float* __restrict__ b1,
    const float* __restrict__ w2, const float* __restrict__ b2,
    const float* __restrict__ fcw, const float* __restrict__ fcb,
    float* __restrict__ out_masks)
{
    extern __shared__ float esm[];
    float* sw1 = esm;            // 2304
    float* sw2 = sw1 + 2304;     // 9216
    float* s0  = sw2 + 9216;     // 4*512
    float* o1  = s0 + 2048;      // 4*1152
    float* o2  = o1 + 4608;      // 4*512
    // total 20224 floats = 80896 B

    int t = threadIdx.x;
    int rbase = blockIdx.x * 4;

    for (int i = t; i < 2304; i += 256) sw1[i] = w1[i];
    for (int i = t; i < 9216; i += 256) sw2[i] = w2[i];
    for (int i = t; i < 2048; i += 256) {
        int rr = i >> 9;
        s0[i] = s_h[(rbase + rr) * 65536 + (i & 511)];   // frame t=0
    }
    for (int i = t; i < 512; i += 256) {
        int rr = i >> 7, tt = i & 127;
        int v = a_h[(rbase + rr) * 128 + tt];
        out_masks[(rbase + rr) * 128 + tt] = (v != (AA_ - 1)) ? 1.f : 0.f;
    }
    __syncthreads();

    // conv1: tasks = rr(4) x oc(32) x y(6) = 768; each computes 6 x-positions
    for (int task = t; task < 768; task += 256) {
        int rr = task / 192, j = task % 192;
        int oc = j / 6, y = j % 6;
        float acc0, acc1, acc2, acc3, acc4, acc5;
        float bb = b1[oc];
        acc0 = acc1 = acc2 = acc3 = acc4 = acc5 = bb;
        const float* sin = s0 + rr * 512;
        const float* kpb = sw1 + oc * 72;
        #pragma unroll
        for (int ic = 0; ic < 8; ic++) {
            #pragma unroll
            for (int ky = 0; ky < 3; ky++) {
                const float* ip = sin + ic * 64 + (y + ky) * 8;
                const float* kp = kpb + ic * 9 + ky * 3;
                float k0 = kp[0], k1 = kp[1], k2 = kp[2];
                float i0 = ip[0], i1 = ip[1], i2 = ip[2], i3 = ip[3];
                float i4 = ip[4], i5 = ip[5], i6 = ip[6], i7 = ip[7];
                acc0 += i0 * k0 + i1 * k1 + i2 * k2;
                acc1 += i1 * k0 + i2 * k1 + i3 * k2;
                acc2 += i2 * k0 + i3 * k1 + i4 * k2;
                acc3 += i3 * k0 + i4 * k1 + i5 * k2;
                acc4 += i4 * k0 + i5 * k1 + i6 * k2;
                acc5 += i5 * k0 + i6 * k1 + i7 * k2;
            }
        }
        float* op = o1 + rr * 1152 + oc * 36 + y * 6;
        op[0] = fmaxf(acc0, 0.f); op[1] = fmaxf(acc1, 0.f);
        op[2] = fmaxf(acc2, 0.f); op[3] = fmaxf(acc3, 0.f);
        op[4] = fmaxf(acc4, 0.f); op[5] = fmaxf(acc5, 0.f);
    }
    __syncthreads();

    // conv2: tasks = rr(4) x oc(32) x y(4) = 512; each computes 4 x-positions
    for (int task = t; task < 512; task += 256) {
        int rr = task >> 7, j = task & 127;
        int oc = j >> 2, y = j & 3;
        float bb = b2[oc];
        float acc0 = bb, acc1 = bb, acc2 = bb, acc3 = bb;
        const float* iin = o1 + rr * 1152;
        const float* kpb = sw2 + oc * 288;
        for (int ic = 0; ic < 32; ic++) {
            #pragma unroll
            for (int ky = 0; ky < 3; ky++) {
                const float* ip = iin + ic * 36 + (y + ky) * 6;
                const float* kp = kpb + ic * 9 + ky * 3;
                float k0 = kp[0], k1 = kp[1], k2 = kp[2];
                float i0 = ip[0], i1 = ip[1], i2 = ip[2];
                float i3 = ip[3], i4 = ip[4], i5 = ip[5];
                acc0 += i0 * k0 + i1 * k1 + i2 * k2;
                acc1 += i1 * k0 + i2 * k1 + i3 * k2;
                acc2 += i2 * k0 + i3 * k1 + i4 * k2;
                acc3 += i3 * k0 + i4 * k1 + i5 * k2;
            }
        }
        float* op = o2 + rr * 512 + oc * 16 + y * 4;
        op[0] = fmaxf(acc0, 0.f); op[1] = fmaxf(acc1, 0.f);
        op[2] = fmaxf(acc2, 0.f); op[3] = fmaxf(acc3, 0.f);
    }
    __syncthreads();

    // fc: tasks = rr(4) x o(64) = 256, one per warp-iteration; coalesced f4
    int w = t >> 5, lane = t & 31;
    for (int task = w; task < 256; task += 8) {
        int rr = task >> 6, o = task & 63;
        const float4* wp = (const float4*)(fcw + o * 512);
        const float4* xp = (const float4*)(o2 + rr * 512);
        float acc = 0.f;
        #pragma unroll
        for (int i = 0; i < 4; i++) {
            float4 a = wp[lane + 32 * i];
            float4 b = xp[lane + 32 * i];
            acc += a.x * b.x + a.y * b.y + a.z * b.z + a.w * b.w;
        }
        #pragma unroll
        for (int d = 16; d > 0; d >>= 1)
            acc += __shfl_xor_sync(0xffffffffu, acc, d);
        if (lane == 0)
            g_state_emb[(rbase + rr) * 64 + o] = fmaxf(acc + fcb[o], 0.f);
    }
}

// ---------------------------------------------------------------------------
// Recurrent rollout v2: 160 blocks x 256 threads (8 warps), 4 rows/block.
// lane = r(2b) + 4*s(3b); slot = w*8+s in 0..63 = the h-dim this lane owns.
// Each lane: GRU gates r/z/n for dim slot (3 dots) + mlp1 dim slot (1 dot)
// + redundant-per-warp mlp2/argmax. f32x2 packed FMAs throughout.
// ---------------------------------------------------------------------------
__global__ void __launch_bounds__(256) recur_kernel(
    const float* __restrict__ b_z, const float* __restrict__ emb,
    const float* __restrict__ wih, const float* __restrict__ whh,
    const float* __restrict__ bih, const float* __restrict__ bhh_g,
    const float* __restrict__ m1w, const float* __restrict__ m1b,
    const float* __restrict__ m2w, const float* __restrict__ m2b,
    float* __restrict__ out_logits)
{
    extern __shared__ float4 sm4[];
    float4* WQ = sm4;                    // [16][192]
    float4* M1 = WQ + 16 * 192;          // [16][64]
    float4* M2 = M1 + 16 * 64;           // [16][8] (o padded to 8, zeros)
    float*  AT = (float*)(M2 + 16 * 8);  // [6][208]
    float*  HS = AT + 6 * 208;           // [2][4][68] h double buffer (544)
    float*  HD = HS + 544;               // [4][68] hid exchange (272)
    float*  XV = HS;                     // temp: [4][128] = [se|bz] per row

    int t = threadIdx.x;
    int w = t >> 5, lane = t & 31;
    int r = lane & 3, s = lane >> 2;
    int d = w * 8 + s;                   // slot / h-dim owned by this lane
    int row = blockIdx.x * 4 + r;

    // ---- stage weights (transposed [k4][o]) ----
    for (int idx = t; idx < 16 * 192; idx += 256) {
        int o = idx >> 4, k4 = idx & 15;
        WQ[k4 * 192 + o] = *(const float4*)(whh + o * 64 + k4 * 4);
    }
    for (int idx = t; idx < 16 * 64; idx += 256) {
        int o = idx >> 4, k4 = idx & 15;
        M1[k4 * 64 + o] = *(const float4*)(m1w + o * 64 + k4 * 4);
    }
    for (int idx = t; idx < 16 * 8; idx += 256) {
        int o = idx >> 4, k4 = idx & 15;
        float4 v = make_float4(0.f, 0.f, 0.f, 0.f);
        if (o < 6) v = *(const float4*)(m2w + o * 64 + k4 * 4);
        M2[k4 * 8 + o] = v;
    }
    for (int idx = t; idx < 6 * 192; idx += 256) {
        int a = idx / 192, o = idx % 192;
        float sum = 0.f;
        #pragma unroll
        for (int j = 0; j < 6; j++) sum += emb[a * 6 + j] * wih[o * 134 + 64 + j];
        AT[a * 208 + o] = sum;
    }
    // stage per-row [state_emb | b_z] into XV (overlaps HS; zeroed later)
    for (int i = t; i < 512; i += 256) {
        int rr = i >> 7, k = i & 127;
        int rw = blockIdx.x * 4 + rr;
        XV[rr * 128 + k] = (k < 64) ? g_state_emb[rw * 64 + k]
                                    : b_z[(rw / 10) * 64 + (k - 64)];
    }
    __syncthreads();

    // ---- per-lane constants: base gx = x-part dot + bih for r/z/n of dim d
    int o0 = d, o1 = d + 64, o2i = d + 128;
    float bg0 = bih[o0], bg1 = bih[o1], bg2 = bih[o2i];
    {
        const float* xv = XV + r * 128;
        const float* w0 = wih + o0 * 134;
        const float* w1r = wih + o1 * 134;
        const float* w2r = wih + o2i * 134;
        for (int k = 0; k < 64; k++) {
            float x = xv[k];
            bg0 += x * w0[k]; bg1 += x * w1r[k]; bg2 += x * w2r[k];
        }
        for (int k = 0; k < 64; k++) {
            float x = xv[64 + k];
            bg0 += x * w0[70 + k]; bg1 += x * w1r[70 + k]; bg2 += x * w2r[70 + k];
        }
    }
    float bh0 = bhh_g[o0], bh1 = bhh_g[o1], bh2 = bhh_g[o2i];
    float mb = m1b[d];
    float lb = (s < 6) ? m2b[s] : 0.f;
    __syncthreads();

    // FULL zero of HS (544) + HD (272) — graph-replay safety
    for (int i = t; i < 544 + 272; i += 256) HS[i] = 0.f;
    __syncthreads();

    float h = 0.f;
    int act = AA_ - 1;
    float* outp = out_logits + row * (TSTEPS * 6);

    const ulonglong2* WQq = (const ulonglong2*)WQ;
    const ulonglong2* M1q = (const ulonglong2*)M1;
    const ulonglong2* M2q = (const ulonglong2*)M2;

    for (int step = 0; step < TSTEPS; step++) {
        int p = step & 1;
        // ---- gh = h @ Whh^T (3 dots: r/z/n of dim d) ----
        u64 ar = 0ull, az = 0ull, an = 0ull;
        const ulonglong2* hp = (const ulonglong2*)(HS + (p * 4 + r) * 68);
        #pragma unroll
        for (int k4 = 0; k4 < 16; k4++) {
            ulonglong2 h2 = hp[k4];
            const ulonglong2* wq = WQq + k4 * 192;
            ulonglong2 v;
            v = wq[o0];  fma2(ar, h2.x, v.x); fma2(ar, h2.y, v.y);
            v = wq[o1];  fma2(az, h2.x, v.x); fma2(az, h2.y, v.y);
            v = wq[o2i]; fma2(an, h2.x, v.x); fma2(an, h2.y, v.y);
        }
        const float* atr = AT + act * 208;
        float ghr = hsum2(ar) + bh0;
        float ghz = hsum2(az) + bh1;
        float ghn = hsum2(an) + bh2;
        float rg = fsigm(bg0 + atr[o0] + ghr);
        float zg = fsigm(bg1 + atr[o1] + ghz);
        float ng = tanhf(bg2 + atr[o2i] + rg * ghn);
        float hn = (1.f - zg) * ng + zg * h;
        h = hn;
        HS[((p ^ 1) * 4 + r) * 68 + d] = hn;
        __syncthreads();

        // ---- mlp1: one output dim per lane ----
        u64 am = 0ull;
        const ulonglong2* hq = (const ulonglong2*)(HS + ((p ^ 1) * 4 + r) * 68);
        #pragma unroll
        for (int k4 = 0; k4 < 16; k4++) {
            ulonglong2 h2 = hq[k4];
            ulonglong2 v = M1q[k4 * 64 + d];
            fma2(am, h2.x, v.x); fma2(am, h2.y, v.y);
        }
        HD[r * 68 + d] = tanhf(hsum2(am) + mb);
        __syncthreads();

        // ---- mlp2 + argmax (redundant per warp; no 3rd barrier) ----
        u64 al = 0ull;
        const ulonglong2* hdq = (const ulonglong2*)(HD + r * 68);
        #pragma unroll
        for (int k4 = 0; k4 < 16; k4++) {
            ulonglong2 h2 = hdq[k4];
            ulonglong2 v = M2q[k4 * 8 + s];
            fma2(al, h2.x, v.x); fma2(al, h2.y, v.y);
        }
        float lacc = hsum2(al) + lb;
        if (w == 0 && s < 6) outp[step * 6 + s] = lacc;

        float bv = (s < 6) ? lacc : -3.0e38f;
        int bi = s;
        #pragma unroll
        for (int dd = 4; dd < 32; dd <<= 1) {   // butterfly over s bits
            float ov = __shfl_xor_sync(0xffffffffu, bv, dd);
            int   oi = __shfl_xor_sync(0xffffffffu, bi, dd);
            if (ov > bv || (ov == bv && oi < bi)) { bv = ov; bi = oi; }
        }
        act = bi;  // first-max tie-break, matching jnp.argmax
    }
}

extern "C" void kernel_launch(void* const* d_in, const int* in_sizes, int n_in,
                              void* d_out, int out_size) {
    const float* s_h = (const float*)d_in[0];
    const int*   a_h = (const int*)  d_in[1];
    const float* b_z = (const float*)d_in[2];
    const float* w1  = (const float*)d_in[3];
    const float* b1  = (const float*)d_in[4];
    const float* w2  = (const float*)d_in[5];
    const float* b2  = (const float*)d_in[6];
    const float* fcw = (const float*)d_in[7];
    const float* fcb = (const float*)d_in[8];
    const float* emb = (const float*)d_in[9];
    const float* wih = (const float*)d_in[10];
    const float* whh = (const float*)d_in[11];
    const float* bih = (const float*)d_in[12];
    const float* bhh = (const float*)d_in[13];
    const float* m1w = (const float*)d_in[14];
    const float* m1b = (const float*)d_in[15];
    const float* m2w = (const float*)d_in[16];
    const float* m2b = (const float*)d_in[17];

    float* out = (float*)d_out;
    float* out_logits = out;                       // [B,N,T-1,A]
    float* out_masks  = out + BN_ * TSTEPS * AA_;  // [B,N,T,1]

    static const size_t ENC_SMEM = 20224 * sizeof(float);   // ~79 KB
    static const size_t RECUR_SMEM =
        (16 * 192 + 16 * 64 + 16 * 8) * sizeof(float4) +
        (6 * 208 + 544 + 272) * sizeof(float);               // ~74 KB
    cudaFuncSetAttribute(encoder_kernel,
                         cudaFuncAttributeMaxDynamicSharedMemorySize,
                         (int)ENC_SMEM);
    cudaFuncSetAttribute(recur_kernel,
                         cudaFuncAttributeMaxDynamicSharedMemorySize,
                         (int)RECUR_SMEM);

    encoder_kernel<<<160, 256, ENC_SMEM>>>(s_h, a_h, w1, b1, w2, b2,
                                           fcw, fcb, out_masks);
    recur_kernel<<<160, 256, RECUR_SMEM>>>(b_z, emb, wih, whh, bih, bhh,
                                           m1w, m1b, m2w, m2b, out_logits);
}

// round 5
// speedup vs baseline: 1.0774x; 1.0774x over previous
#include <cuda_runtime.h>
#include <cuda_bf16.h>

#define BN_ 640
#define TSTEPS 127
#define AA_ 6

typedef unsigned long long u64;

// scratch (device global: no allocations allowed)
__device__ float g_state_emb[BN_ * 64];

__device__ __forceinline__ float fsigm(float x) {
    return 1.f / (1.f + expf(-x));
}
__device__ __forceinline__ void fma2(u64& d, u64 a, u64 b) {
    asm("fma.rn.f32x2 %0, %1, %2, %0;" : "+l"(d) : "l"(a), "l"(b));
}
__device__ __forceinline__ float hsum2(u64 v) {
    unsigned lo, hi;
    asm("mov.b64 {%0,%1}, %2;" : "=r"(lo), "=r"(hi) : "l"(v));
    return __uint_as_float(lo) + __uint_as_float(hi);
}

// ---------------------------------------------------------------------------
// Encoder v3: 320 blocks x 256 threads, 2 rows/block.
// ---------------------------------------------------------------------------
__global__ void __launch_bounds__(256) encoder_kernel(
    const float* __restrict__ s_h, const int* __restrict__ a_h,
    const float* __restrict__ w1, const float* __restrict__ b1,
    const float* __restrict__ w2, const float* __restrict__ b2,
    const float* __restrict__ fcw, const float* __restrict__ fcb,
    float* __restrict__ out_masks)
{
    extern __shared__ float esm[];
    float* sw1 = esm;            // 2304
    float* sw2 = sw1 + 2304;     // 9216
    float* s0  = sw2 + 9216;     // 2*512
    float* o1  = s0 + 1024;      // 2*1152
    float* o2  = o1 + 2304;      // 2*512
    // total 15872 floats = 63.5 KB

    int t = threadIdx.x;
    int rbase = blockIdx.x * 2;

    for (int i = t; i < 2304; i += 256) sw1[i] = w1[i];
    for (int i = t; i < 9216; i += 256) sw2[i] = w2[i];
    for (int i = t; i < 1024; i += 256) {
        int rr = i >> 9;
        s0[i] = s_h[(rbase + rr) * 65536 + (i & 511)];   // frame t=0
    }
    for (int i = t; i < 256; i += 256) {
        int rr = i >> 7, tt = i & 127;
        int v = a_h[(rbase + rr) * 128 + tt];
        out_masks[(rbase + rr) * 128 + tt] = (v != (AA_ - 1)) ? 1.f : 0.f;
    }
    __syncthreads();

    // conv1: tasks = rr(2) x oc(32) x y(6) = 384; each computes 6 x-positions
    for (int task = t; task < 384; task += 256) {
        int rr = task / 192, j = task % 192;
        int oc = j / 6, y = j % 6;
        float bb = b1[oc];
        float acc0 = bb, acc1 = bb, acc2 = bb, acc3 = bb, acc4 = bb, acc5 = bb;
        const float* sin = s0 + rr * 512;
        const float* kpb = sw1 + oc * 72;
        #pragma unroll
        for (int ic = 0; ic < 8; ic++) {
            #pragma unroll
            for (int ky = 0; ky < 3; ky++) {
                const float* ip = sin + ic * 64 + (y + ky) * 8;
                const float* kp = kpb + ic * 9 + ky * 3;
                float k0 = kp[0], k1 = kp[1], k2 = kp[2];
                float i0 = ip[0], i1 = ip[1], i2 = ip[2], i3 = ip[3];
                float i4 = ip[4], i5 = ip[5], i6 = ip[6], i7 = ip[7];
                acc0 += i0 * k0 + i1 * k1 + i2 * k2;
                acc1 += i1 * k0 + i2 * k1 + i3 * k2;
                acc2 += i2 * k0 + i3 * k1 + i4 * k2;
                acc3 += i3 * k0 + i4 * k1 + i5 * k2;
                acc4 += i4 * k0 + i5 * k1 + i6 * k2;
                acc5 += i5 * k0 + i6 * k1 + i7 * k2;
            }
        }
        float* op = o1 + rr * 1152 + oc * 36 + y * 6;
        op[0] = fmaxf(acc0, 0.f); op[1] = fmaxf(acc1, 0.f);
        op[2] = fmaxf(acc2, 0.f); op[3] = fmaxf(acc3, 0.f);
        op[4] = fmaxf(acc4, 0.f); op[5] = fmaxf(acc5, 0.f);
    }
    __syncthreads();

    // conv2: tasks = rr(2) x oc(32) x y(4) = 256; 1 per thread
    {
        int task = t;
        int rr = task >> 7, j = task & 127;
        int oc = j >> 2, y = j & 3;
        float bb = b2[oc];
        float acc0 = bb, acc1 = bb, acc2 = bb, acc3 = bb;
        const float* iin = o1 + rr * 1152;
        const float* kpb = sw2 + oc * 288;
        #pragma unroll 4
        for (int ic = 0; ic < 32; ic++) {
            #pragma unroll
            for (int ky = 0; ky < 3; ky++) {
                const float* ip = iin + ic * 36 + (y + ky) * 6;
                const float* kp = kpb + ic * 9 + ky * 3;
                float k0 = kp[0], k1 = kp[1], k2 = kp[2];
                float i0 = ip[0], i1 = ip[1], i2 = ip[2];
                float i3 = ip[3], i4 = ip[4], i5 = ip[5];
                acc0 += i0 * k0 + i1 * k1 + i2 * k2;
                acc1 += i1 * k0 + i2 * k1 + i3 * k2;
                acc2 += i2 * k0 + i3 * k1 + i4 * k2;
                acc3 += i3 * k0 + i4 * k1 + i5 * k2;
            }
        }
        float* op = o2 + rr * 512 + oc * 16 + y * 4;
        op[0] = fmaxf(acc0, 0.f); op[1] = fmaxf(acc1, 0.f);
        op[2] = fmaxf(acc2, 0.f); op[3] = fmaxf(acc3, 0.f);
    }
    __syncthreads();

    // fc: tasks = rr(2) x o(64) = 128, warp-cooperative, coalesced float4
    int w = t >> 5, lane = t & 31;
    for (int task = w; task < 128; task += 8) {
        int rr = task >> 6, o = task & 63;
        const float4* wp = (const float4*)(fcw + o * 512);
        const float4* xp = (const float4*)(o2 + rr * 512);
        float acc = 0.f;
        #pragma unroll
        for (int i = 0; i < 4; i++) {
            float4 a = wp[lane + 32 * i];
            float4 b = xp[lane + 32 * i];
            acc += a.x * b.x + a.y * b.y + a.z * b.z + a.w * b.w;
        }
        #pragma unroll
        for (int d = 16; d > 0; d >>= 1)
            acc += __shfl_xor_sync(0xffffffffu, acc, d);
        if (lane == 0)
            g_state_emb[(rbase + rr) * 64 + o] = fmaxf(acc + fcb[o], 0.f);
    }
}

// ---------------------------------------------------------------------------
// Recurrent rollout v3: 160 blocks x 256 threads (8 warps), 4 rows/block.
// lane = r(2b) + 4*s(3b); d = w*8+s = h-dim owned by this lane.
// GEMM loops use explicit 16-load batches (4 h + 12 w) so LDS latency is
// overlapped (MLP~16 instead of ~1), with split accumulator chains.
// ---------------------------------------------------------------------------
__global__ void __launch_bounds__(256, 2) recur_kernel(
    const float* __restrict__ b_z, const float* __restrict__ emb,
    const float* __restrict__ wih, const float* __restrict__ whh,
    const float* __restrict__ bih, const float* __restrict__ bhh_g,
    const float* __restrict__ m1w, const float* __restrict__ m1b,
    const float* __restrict__ m2w, const float* __restrict__ m2b,
    float* __restrict__ out_logits)
{
    extern __shared__ float4 sm4[];
    float4* WQ = sm4;                    // [16][192]
    float4* M1 = WQ + 16 * 192;          // [16][64]
    float4* M2 = M1 + 16 * 64;           // [16][8] (o padded to 8, zeros)
    float*  AT = (float*)(M2 + 16 * 8);  // [6][208]
    float*  HS = AT + 6 * 208;           // [2][4][68] h double buffer (544)
    float*  HD = HS + 544;               // [4][68] hid exchange (272)
    float*  XV = HS;                     // temp: [4][128] = [se|bz] per row

    int t = threadIdx.x;
    int w = t >> 5, lane = t & 31;
    int r = lane & 3, s = lane >> 2;
    int d = w * 8 + s;
    int row = blockIdx.x * 4 + r;

    // ---- stage weights (transposed [k4][o]) ----
    for (int idx = t; idx < 16 * 192; idx += 256) {
        int o = idx >> 4, k4 = idx & 15;
        WQ[k4 * 192 + o] = *(const float4*)(whh + o * 64 + k4 * 4);
    }
    for (int idx = t; idx < 16 * 64; idx += 256) {
        int o = idx >> 4, k4 = idx & 15;
        M1[k4 * 64 + o] = *(const float4*)(m1w + o * 64 + k4 * 4);
    }
    for (int idx = t; idx < 16 * 8; idx += 256) {
        int o = idx >> 4, k4 = idx & 15;
        float4 v = make_float4(0.f, 0.f, 0.f, 0.f);
        if (o < 6) v = *(const float4*)(m2w + o * 64 + k4 * 4);
        M2[k4 * 8 + o] = v;
    }
    for (int idx = t; idx < 6 * 192; idx += 256) {
        int a = idx / 192, o = idx % 192;
        float sum = 0.f;
        #pragma unroll
        for (int j = 0; j < 6; j++) sum += emb[a * 6 + j] * wih[o * 134 + 64 + j];
        AT[a * 208 + o] = sum;
    }
    // stage per-row [state_emb | b_z] into XV (overlaps HS; zeroed later)
    for (int i = t; i < 512; i += 256) {
        int rr = i >> 7, k = i & 127;
        int rw = blockIdx.x * 4 + rr;
        XV[rr * 128 + k] = (k < 64) ? g_state_emb[rw * 64 + k]
                                    : b_z[(rw / 10) * 64 + (k - 64)];
    }
    __syncthreads();

    // ---- per-lane constants: base gx = x-part dot + bih for r/z/n of dim d
    int o0 = d, o1 = d + 64, o2i = d + 128;
    float bg0 = bih[o0], bg1 = bih[o1], bg2 = bih[o2i];
    {
        const float* xv = XV + r * 128;
        const float* w0 = wih + o0 * 134;
        const float* w1r = wih + o1 * 134;
        const float* w2r = wih + o2i * 134;
        for (int k = 0; k < 64; k++) {
            float x = xv[k];
            bg0 += x * w0[k]; bg1 += x * w1r[k]; bg2 += x * w2r[k];
        }
        for (int k = 0; k < 64; k++) {
            float x = xv[64 + k];
            bg0 += x * w0[70 + k]; bg1 += x * w1r[70 + k]; bg2 += x * w2r[70 + k];
        }
    }
    float bh0 = bhh_g[o0], bh1 = bhh_g[o1], bh2 = bhh_g[o2i];
    float mb = m1b[d];
    float lb = (s < 6) ? m2b[s] : 0.f;
    __syncthreads();

    // FULL zero of HS (544) + HD (272) — graph-replay safety
    for (int i = t; i < 544 + 272; i += 256) HS[i] = 0.f;
    __syncthreads();

    float h = 0.f;
    int act = AA_ - 1;
    float* outp = out_logits + row * (TSTEPS * 6);

    const ulonglong2* WQq = (const ulonglong2*)WQ;
    const ulonglong2* M1q = (const ulonglong2*)M1;
    const ulonglong2* M2q = (const ulonglong2*)M2;

    for (int step = 0; step < TSTEPS; step++) {
        int p = step & 1;
        // ---- gh = h @ Whh^T (r/z/n of dim d), batched 4 k4 per iter ----
        u64 ar = 0ull, az = 0ull, an = 0ull;
        u64 br = 0ull, bz2 = 0ull, bn = 0ull;
        const ulonglong2* hp = (const ulonglong2*)(HS + (p * 4 + r) * 68);
        #pragma unroll
        for (int k4 = 0; k4 < 16; k4 += 4) {
            ulonglong2 h0 = hp[k4], h1 = hp[k4 + 1];
            ulonglong2 h2 = hp[k4 + 2], h3 = hp[k4 + 3];
            const ulonglong2* wp0 = WQq + k4 * 192;
            ulonglong2 a0 = wp0[o0],        c0 = wp0[o1],        e0 = wp0[o2i];
            ulonglong2 a1 = wp0[192 + o0],  c1 = wp0[192 + o1],  e1 = wp0[192 + o2i];
            ulonglong2 a2 = wp0[384 + o0],  c2 = wp0[384 + o1],  e2 = wp0[384 + o2i];
            ulonglong2 a3 = wp0[576 + o0],  c3 = wp0[576 + o1],  e3 = wp0[576 + o2i];
            fma2(ar, h0.x, a0.x); fma2(ar, h0.y, a0.y);
            fma2(az, h0.x, c0.x); fma2(az, h0.y, c0.y);
            fma2(an, h0.x, e0.x); fma2(an, h0.y, e0.y);
            fma2(br, h1.x, a1.x); fma2(br, h1.y, a1.y);
            fma2(bz2, h1.x, c1.x); fma2(bz2, h1.y, c1.y);
            fma2(bn, h1.x, e1.x); fma2(bn, h1.y, e1.y);
            fma2(ar, h2.x, a2.x); fma2(ar, h2.y, a2.y);
            fma2(az, h2.x, c2.x); fma2(az, h2.y, c2.y);
            fma2(an, h2.x, e2.x); fma2(an, h2.y, e2.y);
            fma2(br, h3.x, a3.x); fma2(br, h3.y, a3.y);
            fma2(bz2, h3.x, c3.x); fma2(bz2, h3.y, c3.y);
            fma2(bn, h3.x, e3.x); fma2(bn, h3.y, e3.y);
        }
        const float* atr = AT + act * 208;
        float ghr = hsum2(ar) + hsum2(br) + bh0;
        float ghz = hsum2(az) + hsum2(bz2) + bh1;
        float ghn = hsum2(an) + hsum2(bn) + bh2;
        float rg = fsigm(bg0 + atr[o0] + ghr);
        float zg = fsigm(bg1 + atr[o1] + ghz);
        float ng = tanhf(bg2 + atr[o2i] + rg * ghn);
        float hn = (1.f - zg) * ng + zg * h;
        h = hn;
        HS[((p ^ 1) * 4 + r) * 68 + d] = hn;
        __syncthreads();

        // ---- mlp1: one output dim per lane, batched ----
        u64 am = 0ull, bm = 0ull;
        const ulonglong2* hq = (const ulonglong2*)(HS + ((p ^ 1) * 4 + r) * 68);
        #pragma unroll
        for (int k4 = 0; k4 < 16; k4 += 4) {
            ulonglong2 h0 = hq[k4], h1 = hq[k4 + 1];
            ulonglong2 h2 = hq[k4 + 2], h3 = hq[k4 + 3];
            ulonglong2 v0 = M1q[k4 * 64 + d];
            ulonglong2 v1 = M1q[(k4 + 1) * 64 + d];
            ulonglong2 v2 = M1q[(k4 + 2) * 64 + d];
            ulonglong2 v3 = M1q[(k4 + 3) * 64 + d];
            fma2(am, h0.x, v0.x); fma2(am, h0.y, v0.y);
            fma2(bm, h1.x, v1.x); fma2(bm, h1.y, v1.y);
            fma2(am, h2.x, v2.x); fma2(am, h2.y, v2.y);
            fma2(bm, h3.x, v3.x); fma2(bm, h3.y, v3.y);
        }
        HD[r * 68 + d] = tanhf(hsum2(am) + hsum2(bm) + mb);
        __syncthreads();

        // ---- mlp2 + argmax (redundant per warp; no 3rd barrier) ----
        u64 al = 0ull, bl = 0ull;
        const ulonglong2* hdq = (const ulonglong2*)(HD + r * 68);
        #pragma unroll
        for (int k4 = 0; k4 < 16; k4 += 4) {
            ulonglong2 h0 = hdq[k4], h1 = hdq[k4 + 1];
            ulonglong2 h2 = hdq[k4 + 2], h3 = hdq[k4 + 3];
            ulonglong2 v0 = M2q[k4 * 8 + s];
            ulonglong2 v1 = M2q[(k4 + 1) * 8 + s];
            ulonglong2 v2 = M2q[(k4 + 2) * 8 + s];
            ulonglong2 v3 = M2q[(k4 + 3) * 8 + s];
            fma2(al, h0.x, v0.x); fma2(al, h0.y, v0.y);
            fma2(bl, h1.x, v1.x); fma2(bl, h1.y, v1.y);
            fma2(al, h2.x, v2.x); fma2(al, h2.y, v2.y);
            fma2(bl, h3.x, v3.x); fma2(bl, h3.y, v3.y);
        }
        float lacc = hsum2(al) + hsum2(bl) + lb;
        if (w == 0 && s < 6) outp[step * 6 + s] = lacc;

        float bv = (s < 6) ? lacc : -3.0e38f;
        int bi = s;
        #pragma unroll
        for (int dd = 4; dd < 32; dd <<= 1) {   // butterfly over s bits
            float ov = __shfl_xor_sync(0xffffffffu, bv, dd);
            int   oi = __shfl_xor_sync(0xffffffffu, bi, dd);
            if (ov > bv || (ov == bv && oi < bi)) { bv = ov; bi = oi; }
        }
        act = bi;  // first-max tie-break, matching jnp.argmax
    }
}

extern "C" void kernel_launch(void* const* d_in, const int* in_sizes, int n_in,
                              void* d_out, int out_size) {
    const float* s_h = (const float*)d_in[0];
    const int*   a_h = (const int*)  d_in[1];
    const float* b_z = (const float*)d_in[2];
    const float* w1  = (const float*)d_in[3];
    const float* b1  = (const float*)d_in[4];
    const float* w2  = (const float*)d_in[5];
    const float* b2  = (const float*)d_in[6];
    const float* fcw = (const float*)d_in[7];
    const float* fcb = (const float*)d_in[8];
    const float* emb = (const float*)d_in[9];
    const float* wih = (const float*)d_in[10];
    const float* whh = (const float*)d_in[11];
    const float* bih = (const float*)d_in[12];
    const float* bhh = (const float*)d_in[13];
    const float* m1w = (const float*)d_in[14];
    const float* m1b = (const float*)d_in[15];
    const float* m2w = (const float*)d_in[16];
    const float* m2b = (const float*)d_in[17];

    float* out = (float*)d_out;
    float* out_logits = out;                       // [B,N,T-1,A]
    float* out_masks  = out + BN_ * TSTEPS * AA_;  // [B,N,T,1]

    static const size_t ENC_SMEM = 15872 * sizeof(float);   // ~63.5 KB
    static const size_t RECUR_SMEM =
        (16 * 192 + 16 * 64 + 16 * 8) * sizeof(float4) +
        (6 * 208 + 544 + 272) * sizeof(float);               // ~74 KB
    cudaFuncSetAttribute(encoder_kernel,
                         cudaFuncAttributeMaxDynamicSharedMemorySize,
                         (int)ENC_SMEM);
    cudaFuncSetAttribute(recur_kernel,
                         cudaFuncAttributeMaxDynamicSharedMemorySize,
                         (int)RECUR_SMEM);

    encoder_kernel<<<320, 256, ENC_SMEM>>>(s_h, a_h, w1, b1, w2, b2,
                                           fcw, fcb, out_masks);
    recur_kernel<<<160, 256, RECUR_SMEM>>>(b_z, emb, wih, whh, bih, bhh,
                                           m1w, m1b, m2w, m2b, out_logits);
}

// round 6
// speedup vs baseline: 1.7421x; 1.6169x over previous
#include <cuda_runtime.h>
#include <cuda_bf16.h>

#define BN_ 640
#define TSTEPS 127
#define AA_ 6

typedef unsigned long long u64;

// scratch (device global: no allocations allowed)
__device__ float g_state_emb[BN_ * 64];

__device__ __forceinline__ float fsigm(float x) {
    return 1.f / (1.f + expf(-x));
}
__device__ __forceinline__ void fma2(u64& d, u64 a, u64 b) {
    asm("fma.rn.f32x2 %0, %1, %2, %0;" : "+l"(d) : "l"(a), "l"(b));
}
__device__ __forceinline__ float hsum2(u64 v) {
    unsigned lo, hi;
    asm("mov.b64 {%0,%1}, %2;" : "=r"(lo), "=r"(hi) : "l"(v));
    return __uint_as_float(lo) + __uint_as_float(hi);
}

// ---------------------------------------------------------------------------
// Encoder (unchanged from R5): 320 blocks x 256 threads, 2 rows/block.
// ---------------------------------------------------------------------------
__global__ void __launch_bounds__(256) encoder_kernel(
    const float* __restrict__ s_h, const int* __restrict__ a_h,
    const float* __restrict__ w1, const float* __restrict__ b1,
    const float* __restrict__ w2, const float* __restrict__ b2,
    const float* __restrict__ fcw, const float* __restrict__ fcb,
    float* __restrict__ out_masks)
{
    extern __shared__ float esm[];
    float* sw1 = esm;            // 2304
    float* sw2 = sw1 + 2304;     // 9216
    float* s0  = sw2 + 9216;     // 2*512
    float* o1  = s0 + 1024;      // 2*1152
    float* o2  = o1 + 2304;      // 2*512

    int t = threadIdx.x;
    int rbase = blockIdx.x * 2;

    for (int i = t; i < 2304; i += 256) sw1[i] = w1[i];
    for (int i = t; i < 9216; i += 256) sw2[i] = w2[i];
    for (int i = t; i < 1024; i += 256) {
        int rr = i >> 9;
        s0[i] = s_h[(rbase + rr) * 65536 + (i & 511)];
    }
    {
        int rr = t >> 7, tt = t & 127;
        int v = a_h[(rbase + rr) * 128 + tt];
        out_masks[(rbase + rr) * 128 + tt] = (v != (AA_ - 1)) ? 1.f : 0.f;
    }
    __syncthreads();

    for (int task = t; task < 384; task += 256) {
        int rr = task / 192, j = task % 192;
        int oc = j / 6, y = j % 6;
        float bb = b1[oc];
        float acc0 = bb, acc1 = bb, acc2 = bb, acc3 = bb, acc4 = bb, acc5 = bb;
        const float* sin = s0 + rr * 512;
        const float* kpb = sw1 + oc * 72;
        #pragma unroll
        for (int ic = 0; ic < 8; ic++) {
            #pragma unroll
            for (int ky = 0; ky < 3; ky++) {
                const float* ip = sin + ic * 64 + (y + ky) * 8;
                const float* kp = kpb + ic * 9 + ky * 3;
                float k0 = kp[0], k1 = kp[1], k2 = kp[2];
                float i0 = ip[0], i1 = ip[1], i2 = ip[2], i3 = ip[3];
                float i4 = ip[4], i5 = ip[5], i6 = ip[6], i7 = ip[7];
                acc0 += i0 * k0 + i1 * k1 + i2 * k2;
                acc1 += i1 * k0 + i2 * k1 + i3 * k2;
                acc2 += i2 * k0 + i3 * k1 + i4 * k2;
                acc3 += i3 * k0 + i4 * k1 + i5 * k2;
                acc4 += i4 * k0 + i5 * k1 + i6 * k2;
                acc5 += i5 * k0 + i6 * k1 + i7 * k2;
            }
        }
        float* op = o1 + rr * 1152 + oc * 36 + y * 6;
        op[0] = fmaxf(acc0, 0.f); op[1] = fmaxf(acc1, 0.f);
        op[2] = fmaxf(acc2, 0.f); op[3] = fmaxf(acc3, 0.f);
        op[4] = fmaxf(acc4, 0.f); op[5] = fmaxf(acc5, 0.f);
    }
    __syncthreads();

    {
        int task = t;
        int rr = task >> 7, j = task & 127;
        int oc = j >> 2, y = j & 3;
        float bb = b2[oc];
        float acc0 = bb, acc1 = bb, acc2 = bb, acc3 = bb;
        const float* iin = o1 + rr * 1152;
        const float* kpb = sw2 + oc * 288;
        #pragma unroll 4
        for (int ic = 0; ic < 32; ic++) {
            #pragma unroll
            for (int ky = 0; ky < 3; ky++) {
                const float* ip = iin + ic * 36 + (y + ky) * 6;
                const float* kp = kpb + ic * 9 + ky * 3;
                float k0 = kp[0], k1 = kp[1], k2 = kp[2];
                float i0 = ip[0], i1 = ip[1], i2 = ip[2];
                float i3 = ip[3], i4 = ip[4], i5 = ip[5];
                acc0 += i0 * k0 + i1 * k1 + i2 * k2;
                acc1 += i1 * k0 + i2 * k1 + i3 * k2;
                acc2 += i2 * k0 + i3 * k1 + i4 * k2;
                acc3 += i3 * k0 + i4 * k1 + i5 * k2;
            }
        }
        float* op = o2 + rr * 512 + oc * 16 + y * 4;
        op[0] = fmaxf(acc0, 0.f); op[1] = fmaxf(acc1, 0.f);
        op[2] = fmaxf(acc2, 0.f); op[3] = fmaxf(acc3, 0.f);
    }
    __syncthreads();

    int w = t >> 5, lane = t & 31;
    for (int task = w; task < 128; task += 8) {
        int rr = task >> 6, o = task & 63;
        const float4* wp = (const float4*)(fcw + o * 512);
        const float4* xp = (const float4*)(o2 + rr * 512);
        float acc = 0.f;
        #pragma unroll
        for (int i = 0; i < 4; i++) {
            float4 a = wp[lane + 32 * i];
            float4 b = xp[lane + 32 * i];
            acc += a.x * b.x + a.y * b.y + a.z * b.z + a.w * b.w;
        }
        #pragma unroll
        for (int d = 16; d > 0; d >>= 1)
            acc += __shfl_xor_sync(0xffffffffu, acc, d);
        if (lane == 0)
            g_state_emb[(rbase + rr) * 64 + o] = fmaxf(acc + fcb[o], 0.f);
    }
}

// ---------------------------------------------------------------------------
// Recurrent rollout v4: WEIGHTS IN REGISTERS.
// 160 blocks x 256 threads, 4 rows/block.
// Dot role:   thread t<192 owns GRU row o=t (Whh[o][:] in 64 regs),
//             t in [192,256) owns mlp1 row d=t-192 (m1w[d][:] in 64 regs).
//             Each computes its dot for all 4 rows (h via uniform smem loads).
// Pointwise:  thread t handles (r=t>>6, d=t&63): gate math + h update.
// Per step:   bar; [GRU dots(i) || mlp1/mlp2/argmax(i-1)]; bar; pointwise(i).
// ---------------------------------------------------------------------------
__global__ void __launch_bounds__(256, 2) recur_kernel(
    const float* __restrict__ b_z, const float* __restrict__ emb,
    const float* __restrict__ wih, const float* __restrict__ whh,
    const float* __restrict__ bih, const float* __restrict__ bhh_g,
    const float* __restrict__ m1w, const float* __restrict__ m1b,
    const float* __restrict__ m2w, const float* __restrict__ m2b,
    float* __restrict__ out_logits)
{
    __shared__ __align__(16) float AT[6 * 208];   // act table
    __shared__ __align__(16) float GH[4 * 192];   // gh exchange
    __shared__ __align__(16) float HN[4 * 68];    // h state (stride 68 = 17 u64x2)
    __shared__ __align__(16) float HID[4 * 68];   // hid exchange
    __shared__ __align__(16) float M2S[6 * 64];   // mlp2 weights
    __shared__ __align__(16) float XV[4 * 128];   // [se|bz] preamble
    __shared__ int ACTS[4];

    int t = threadIdx.x;
    int rbase = blockIdx.x * 4;
    int pr = t >> 6, pd = t & 63;                  // pointwise role

    // ---- stage small tables ----
    for (int idx = t; idx < 6 * 192; idx += 256) {
        int a = idx / 192, o = idx % 192;
        float sum = 0.f;
        #pragma unroll
        for (int j = 0; j < 6; j++) sum += emb[a * 6 + j] * wih[o * 134 + 64 + j];
        AT[a * 208 + o] = sum;
    }
    for (int i = t; i < 6 * 64; i += 256) M2S[i] = m2w[i];
    for (int i = t; i < 512; i += 256) {
        int rr = i >> 7, k = i & 127;
        XV[rr * 128 + k] = (k < 64) ? g_state_emb[(rbase + rr) * 64 + k]
                                    : b_z[((rbase + rr) / 10) * 64 + (k - 64)];
    }
    if (t < 4 * 68) HN[t] = 0.f;        // fresh h each launch (graph-safe)
    if (t < 4) ACTS[t] = AA_ - 1;
    __syncthreads();

    // ---- pointwise preamble: base gx (x-part + bih) for (pr, pd) ----
    float bg0 = bih[pd], bg1 = bih[64 + pd], bg2 = bih[128 + pd];
    {
        const float* xv = XV + pr * 128;
        const float* w0 = wih + pd * 134;
        const float* w1r = wih + (64 + pd) * 134;
        const float* w2r = wih + (128 + pd) * 134;
        for (int k = 0; k < 64; k++) {
            float x = xv[k];
            bg0 += x * w0[k]; bg1 += x * w1r[k]; bg2 += x * w2r[k];
        }
        for (int k = 0; k < 64; k++) {
            float x = xv[64 + k];
            bg0 += x * w0[70 + k]; bg1 += x * w1r[70 + k]; bg2 += x * w2r[70 + k];
        }
    }
    float hreg = 0.f;

    // ---- dot-role weights into registers (once) ----
    bool is_gru = (t < 192);
    ulonglong2 wq[16];
    {
        const ulonglong2* wp = is_gru
            ? (const ulonglong2*)(whh + t * 64)
            : (const ulonglong2*)(m1w + (t - 192) * 64);
        #pragma unroll
        for (int j = 0; j < 16; j++) wq[j] = wp[j];
    }
    float dbias = is_gru ? bhh_g[t] : m1b[t - 192];

    float* outp = out_logits;

    for (int i = 0; i <= TSTEPS; i++) {
        __syncthreads();   // h_new(i-1), act(i-2) settled

        if (is_gru) {
            if (i < TSTEPS) {
                // GRU dot: row o=t over 4 rows, h uniform loads
                u64 a0 = 0ull, a1 = 0ull, a2 = 0ull, a3 = 0ull;
                const ulonglong2* hq = (const ulonglong2*)HN;
                #pragma unroll
                for (int k4 = 0; k4 < 16; k4++) {
                    ulonglong2 x0 = hq[k4];
                    ulonglong2 x1 = hq[17 + k4];
                    ulonglong2 x2 = hq[34 + k4];
                    ulonglong2 x3 = hq[51 + k4];
                    u64 wl = wq[k4].x, wh = wq[k4].y;
                    fma2(a0, x0.x, wl); fma2(a0, x0.y, wh);
                    fma2(a1, x1.x, wl); fma2(a1, x1.y, wh);
                    fma2(a2, x2.x, wl); fma2(a2, x2.y, wh);
                    fma2(a3, x3.x, wl); fma2(a3, x3.y, wh);
                }
                GH[0 * 192 + t] = hsum2(a0) + dbias;
                GH[1 * 192 + t] = hsum2(a1) + dbias;
                GH[2 * 192 + t] = hsum2(a2) + dbias;
                GH[3 * 192 + t] = hsum2(a3) + dbias;
            }
        } else {
            if (i > 0) {
                // mlp1 dot: row d=t-192 over 4 rows (uses h_new(i-1) = HN)
                int d = t - 192;
                u64 a0 = 0ull, a1 = 0ull, a2 = 0ull, a3 = 0ull;
                const ulonglong2* hq = (const ulonglong2*)HN;
                #pragma unroll
                for (int k4 = 0; k4 < 16; k4++) {
                    ulonglong2 x0 = hq[k4];
                    ulonglong2 x1 = hq[17 + k4];
                    ulonglong2 x2 = hq[34 + k4];
                    ulonglong2 x3 = hq[51 + k4];
                    u64 wl = wq[k4].x, wh = wq[k4].y;
                    fma2(a0, x0.x, wl); fma2(a0, x0.y, wh);
                    fma2(a1, x1.x, wl); fma2(a1, x1.y, wh);
                    fma2(a2, x2.x, wl); fma2(a2, x2.y, wh);
                    fma2(a3, x3.x, wl); fma2(a3, x3.y, wh);
                }
                HID[0 * 68 + d] = tanhf(hsum2(a0) + dbias);
                HID[1 * 68 + d] = tanhf(hsum2(a1) + dbias);
                HID[2 * 68 + d] = tanhf(hsum2(a2) + dbias);
                HID[3 * 68 + d] = tanhf(hsum2(a3) + dbias);
                asm volatile("bar.sync 1, 64;" ::: "memory");  // warps 6,7

                // mlp2 + argmax: warp 6 (t in [192,224)), lanes 0..23 active
                if (t < 224) {
                    int idx = t - 192;
                    bool v = (idx < 24);
                    int r2 = idx / 6;
                    int a = idx - r2 * 6;
                    float lacc = -3.0e38f;
                    if (v) {
                        u64 al = 0ull, bl = 0ull;
                        const ulonglong2* hh = (const ulonglong2*)(HID + r2 * 68);
                        const ulonglong2* mm = (const ulonglong2*)(M2S + a * 64);
                        #pragma unroll
                        for (int k4 = 0; k4 < 16; k4 += 2) {
                            ulonglong2 h0 = hh[k4], h1 = hh[k4 + 1];
                            ulonglong2 m0 = mm[k4], m1 = mm[k4 + 1];
                            fma2(al, h0.x, m0.x); fma2(al, h0.y, m0.y);
                            fma2(bl, h1.x, m1.x); fma2(bl, h1.y, m1.y);
                        }
                        lacc = hsum2(al) + hsum2(bl) + m2b[a];
                        outp[((rbase + r2) * TSTEPS + (i - 1)) * 6 + a] = lacc;
                    }
                    // rotate-argmax within each 6-lane group
                    float bv = lacc;
                    int bi = a;
                    int base6 = r2 * 6;
                    #pragma unroll
                    for (int j = 1; j < 6; j++) {
                        int oa = a + j; if (oa >= 6) oa -= 6;
                        int sl = base6 + oa; if (sl > 31) sl = 31;
                        float ov = __shfl_sync(0xffffffffu, lacc, sl);
                        if (v && (ov > bv || (ov == bv && oa < bi))) { bv = ov; bi = oa; }
                    }
                    if (v && a == 0) ACTS[r2] = bi;   // first-max tie-break
                }
            }
        }
        __syncthreads();   // gh(i) + act(i-1) visible

        if (i < TSTEPS) {
            float ghr = GH[pr * 192 + pd];
            float ghz = GH[pr * 192 + 64 + pd];
            float ghn = GH[pr * 192 + 128 + pd];
            const float* atr = AT + ACTS[pr] * 208;
            float rg = fsigm(bg0 + atr[pd] + ghr);
            float zg = fsigm(bg1 + atr[64 + pd] + ghz);
            float ng = tanhf(bg2 + atr[128 + pd] + rg * ghn);
            hreg = (1.f - zg) * ng + zg * hreg;
            HN[pr * 68 + pd] = hreg;
        }
    }
}

extern "C" void kernel_launch(void* const* d_in, const int* in_sizes, int n_in,
                              void* d_out, int out_size) {
    const float* s_h = (const float*)d_in[0];
    const int*   a_h = (const int*)  d_in[1];
    const float* b_z = (const float*)d_in[2];
    const float* w1  = (const float*)d_in[3];
    const float* b1  = (const float*)d_in[4];
    const float* w2  = (const float*)d_in[5];
    const float* b2  = (const float*)d_in[6];
    const float* fcw = (const float*)d_in[7];
    const float* fcb = (const float*)d_in[8];
    const float* emb = (const float*)d_in[9];
    const float* wih = (const float*)d_in[10];
    const float* whh = (const float*)d_in[11];
    const float* bih = (const float*)d_in[12];
    const float* bhh = (const float*)d_in[13];
    const float* m1w = (const float*)d_in[14];
    const float* m1b = (const float*)d_in[15];
    const float* m2w = (const float*)d_in[16];
    const float* m2b = (const float*)d_in[17];

    float* out = (float*)d_out;
    float* out_logits = out;                       // [B,N,T-1,A]
    float* out_masks  = out + BN_ * TSTEPS * AA_;  // [B,N,T,1]

    static const size_t ENC_SMEM = 15872 * sizeof(float);   // ~63.5 KB
    cudaFuncSetAttribute(encoder_kernel,
                         cudaFuncAttributeMaxDynamicSharedMemorySize,
                         (int)ENC_SMEM);

    encoder_kernel<<<320, 256, ENC_SMEM>>>(s_h, a_h, w1, b1, w2, b2,
                                           fcw, fcb, out_masks);
    recur_kernel<<<160, 256>>>(b_z, emb, wih, whh, bih, bhh,
                               m1w, m1b, m2w, m2b, out_logits);
}